// round 1
// baseline (speedup 1.0000x reference)
#include <cuda_runtime.h>
#include <cstdint>

#define DIM   1024
#define NQ    10
#define NWIN  65472   // 16 * 4092
#define NWPB  4092    // windows per batch row
#define LSEQ  4096

typedef unsigned long long ull;

// M transposed: g_Mt[j*DIM + d]  (M = R * E, rotations folded in)
__device__ float g_Mt[DIM * DIM];

// ---------------------------------------------------------------------------
// Kernel 1: M = R * E, stored transposed.
// Each block owns 8 columns of E (a full 1024-row strip in smem), applies the
// 10 RY butterflies along the row (d) index, writes out transposed+coalesced.
// ---------------------------------------------------------------------------
__global__ __launch_bounds__(256) void rot_kernel(const float* __restrict__ E,
                                                  const float* __restrict__ theta) {
    __shared__ float sm[8 * 1028];  // pitch 1028 -> conflict-free (4c+d)%32
    const int tid = threadIdx.x;
    const int j0 = blockIdx.x * 8;

    float ct[NQ], st[NQ];
#pragma unroll
    for (int i = 0; i < NQ; i++) sincosf(0.5f * theta[i], &st[i], &ct[i]);

    // load strip (c fastest -> 32B-granular global reads; tiny kernel, fine)
    for (int idx = tid; idx < 8192; idx += 256) {
        int c = idx & 7, d = idx >> 3;
        sm[c * 1028 + d] = E[d * DIM + j0 + c];
    }
    __syncthreads();

    // qubit i acts on row-bit (9-i):  new0 = ct*a0 - st*a1 ; new1 = st*a0 + ct*a1
    for (int i = 0; i < NQ; i++) {
        const int m = 9 - i;
        for (int t = tid; t < 4096; t += 256) {
            int c = t >> 9, p = t & 511;
            int low = p & ((1 << m) - 1);
            int d0 = ((p >> m) << (m + 1)) | low;
            int d1 = d0 | (1 << m);
            float a0 = sm[c * 1028 + d0];
            float a1 = sm[c * 1028 + d1];
            sm[c * 1028 + d0] = ct[i] * a0 - st[i] * a1;
            sm[c * 1028 + d1] = st[i] * a0 + ct[i] * a1;
        }
        __syncthreads();
    }

    // store transposed, d fastest -> fully coalesced
    for (int idx = tid; idx < 8192; idx += 256) {
        int d = idx & 1023, c = idx >> 10;
        g_Mt[(j0 + c) * DIM + d] = sm[c * 1028 + d];
    }
}

// ---------------------------------------------------------------------------
// Kernel 2: z_n = sum_d sgn(d) * ( sum_j M[d,j]*s_n[j] )^2
// Block: 128 windows x all 1024 d (8 passes of Dt=128), Jt=32 smem tiles.
// s_n[j] = Phi[n][j>>5] * Plo[n][j&31]; with j-tiles 32-aligned the Phi index
// is constant per tile. Inner loop uses packed fma.rn.f32x2 (2 FMA/lane).
// ---------------------------------------------------------------------------
__device__ __forceinline__ void fma2(ull& d, ull a, ull b) {
    asm("fma.rn.f32x2 %0, %1, %2, %0;" : "+l"(d) : "l"(a), "l"(b));
}

#define SM_PHI   0
#define SM_PLO   (128 * 33)
#define SM_MT    (2 * 128 * 33)
#define SM_S2F   (2 * 128 * 33 + 32 * 136)          // float offset of sS2
#define SMEM_FLOATS (SM_S2F + 2 * 32 * 128)          // sS2 is 32*128 ull
#define SMEM_BYTES  (SMEM_FLOATS * 4)                // 83968 B

__global__ __launch_bounds__(256, 2) void qgemm_kernel(const float* __restrict__ x,
                                                       float* __restrict__ out) {
    extern __shared__ float smem[];
    float* Phi = smem + SM_PHI;           // [128][33]  (pad -> (r+j)%32 banks)
    float* Plo = smem + SM_PLO;           // [128][33]
    float* sMt = smem + SM_MT;            // [32][136]  (j-major M tile)
    ull*   sS2 = (ull*)(smem + SM_S2F);   // [32][128]  duplicated {s,s} pairs

    const int tid = threadIdx.x;
    const int tx = tid & 15, ty = tid >> 4;
    const int n0 = blockIdx.x * 128;

    // ---- phase 0: per-window sincos tables -------------------------------
    if (tid < 128) {
        const int r = tid;
        const int n = n0 + r;
        if (n < NWIN) {
            const int b = n / NWPB;
            const int w = n - b * NWPB;
            float cs[2][5], sn[2][5];
#pragma unroll
            for (int c = 0; c < 2; c++)
#pragma unroll
                for (int k = 0; k < 5; k++) {
                    float v = x[((b * 2 + c) << 12) + w + k];
                    sincosf(0.5f * v, &sn[c][k], &cs[c][k]);
                }
#pragma unroll 4
            for (int u = 0; u < 32; u++) {
                float fh = 1.0f, fl = 1.0f;
#pragma unroll
                for (int i = 0; i < 5; i++) {
                    int bit = (u >> (4 - i)) & 1;   // qubit i <-> bit (4-i)
                    fh *= bit ? sn[0][i] : cs[0][i];
                    fl *= bit ? sn[1][i] : cs[1][i];
                }
                Phi[r * 33 + u] = fh;   // qubits 0..4  (c=0,k=0..4), bits 9..5
                Plo[r * 33 + u] = fl;   // qubits 5..9  (c=1,k=0..4), bits 4..0
            }
        } else {
#pragma unroll 4
            for (int u = 0; u < 32; u++) { Phi[r * 33 + u] = 0.0f; Plo[r * 33 + u] = 0.0f; }
        }
    }

    // ---- main loop: 256 chunks = 8 d-passes x 32 j-chunks ----------------
    ull acc[8][4];
    float zp[8];
#pragma unroll
    for (int i = 0; i < 8; i++) {
        zp[i] = 0.0f;
#pragma unroll
        for (int k = 0; k < 4; k++) acc[i][k] = 0ull;
    }

    float4 mreg[4];
#pragma unroll
    for (int q = 0; q < 4; q++) {          // prefetch chunk 0
        int e = tid + q * 256;
        int jj = e >> 5, dd4 = e & 31;
        mreg[q] = *(const float4*)&g_Mt[jj * DIM + dd4 * 4];
    }

    for (int t = 0; t < 256; t++) {
        const int jc = t & 31;
        __syncthreads();
        // commit prefetched M tile (contiguous per-jj rows: conflict-free)
#pragma unroll
        for (int q = 0; q < 4; q++) {
            int e = tid + q * 256;
            int jj = e >> 5, dd4 = e & 31;
            *(float4*)&sMt[jj * 136 + dd4 * 4] = mreg[q];
        }
        // build duplicated s tile: s = Phi[r][jc] * Plo[r][jj]
#pragma unroll
        for (int k = 0; k < 16; k++) {
            int e = tid + k * 256;
            int r = e & 127, jj = e >> 7;
            float s = Phi[r * 33 + jc] * Plo[r * 33 + jj];
            unsigned int bb = __float_as_uint(s);
            sS2[jj * 128 + r] = ((ull)bb << 32) | bb;
        }
        __syncthreads();
        if (t + 1 < 256) {                 // prefetch next chunk (hides L2 lat)
            const int t1 = t + 1;
            const int dp1 = t1 >> 5, jc1 = t1 & 31;
#pragma unroll
            for (int q = 0; q < 4; q++) {
                int e = tid + q * 256;
                int jj = e >> 5, dd4 = e & 31;
                mreg[q] = *(const float4*)&g_Mt[(jc1 * 32 + jj) * DIM + dp1 * 128 + dd4 * 4];
            }
        }
        // inner product over this 32-wide j slab
#pragma unroll
        for (int jj = 0; jj < 32; jj++) {
            const ulonglong2* ap = (const ulonglong2*)(sS2 + jj * 128 + (ty << 3));
            ulonglong2 a01 = ap[0], a23 = ap[1], a45 = ap[2], a67 = ap[3];
            const ulonglong2* bp = (const ulonglong2*)(sMt + jj * 136 + (tx << 3));
            ulonglong2 bA = bp[0], bB = bp[1];
            ull av[8] = {a01.x, a01.y, a23.x, a23.y, a45.x, a45.y, a67.x, a67.y};
            ull bv[4] = {bA.x, bA.y, bB.x, bB.y};
#pragma unroll
            for (int i = 0; i < 8; i++)
#pragma unroll
                for (int k = 0; k < 4; k++) fma2(acc[i][k], av[i], bv[k]);
        }
        // end of a d-pass: square + signed accumulate, reset accumulators
        if ((t & 31) == 31) {
            const int dpass = t >> 5;
            const float sgn = (dpass < 4) ? 1.0f : -1.0f;  // d<512 vs d>=512
#pragma unroll
            for (int i = 0; i < 8; i++)
#pragma unroll
                for (int k = 0; k < 4; k++) {
                    float lo = __uint_as_float((unsigned int)acc[i][k]);
                    float hi = __uint_as_float((unsigned int)(acc[i][k] >> 32));
                    zp[i] += sgn * fmaf(lo, lo, hi * hi);
                    acc[i][k] = 0ull;
                }
        }
    }

    // ---- reduce partial z over the 16 column-groups ----------------------
    __syncthreads();
    float* red = smem;  // reuse Phi/Plo region: [16][128]
#pragma unroll
    for (int i = 0; i < 8; i++) red[tx * 128 + ty * 8 + i] = zp[i];
    __syncthreads();
    if (tid < 128) {
        float z = 0.0f;
#pragma unroll
        for (int q = 0; q < 16; q++) z += red[q * 128 + tid];
        const int n = n0 + tid;
        if (n < NWIN) out[n] = z;
    }
}

// ---------------------------------------------------------------------------
extern "C" void kernel_launch(void* const* d_in, const int* in_sizes, int n_in,
                              void* d_out, int out_size) {
    const float* x     = (const float*)d_in[0];   // (16, 2, 4096)
    const float* E     = (const float*)d_in[1];   // (1024, 1024)
    const float* theta = (const float*)d_in[2];   // (10,)
    float* out = (float*)d_out;                   // 65472 floats

    rot_kernel<<<DIM / 8, 256>>>(E, theta);

    cudaFuncSetAttribute(qgemm_kernel,
                         cudaFuncAttributeMaxDynamicSharedMemorySize, SMEM_BYTES);
    qgemm_kernel<<<(NWIN + 127) / 128, 256, SMEM_BYTES>>>(x, out);
}

// round 5
// speedup vs baseline: 2.6261x; 2.6261x over previous
#include <cuda_runtime.h>
#include <cuda_bf16.h>
#include <cstdint>

#define DIM   1024
#define NQ    10
#define NWIN  65472
#define NWPB  4092
#define NPAD  65536

typedef unsigned long long ull;
typedef unsigned int uint;

// M = R*E split to bf16 hi/lo, layout [d][j]
__device__ __nv_bfloat16 g_Bh[DIM * DIM];
__device__ __nv_bfloat16 g_Bl[DIM * DIM];
// s-state split to bf16 hi/lo, layout [n][j], padded to NPAD rows (zeros past NWIN)
__device__ __nv_bfloat16 g_Ah[(size_t)NPAD * DIM];
__device__ __nv_bfloat16 g_Al[(size_t)NPAD * DIM];

static __device__ __forceinline__ uint smem_u32(const void* p) {
    return (uint)__cvta_generic_to_shared(p);
}
__device__ __forceinline__ void cpasync16(uint dst, const void* src) {
    asm volatile("cp.async.cg.shared.global [%0], [%1], 16;" :: "r"(dst), "l"(src) : "memory");
}
#define CP_COMMIT asm volatile("cp.async.commit_group;" ::: "memory")
#define CP_WAIT1  asm volatile("cp.async.wait_group 1;" ::: "memory")
#define CP_WAIT0  asm volatile("cp.async.wait_group 0;" ::: "memory")

__device__ __forceinline__ void ldsm4(uint* r, uint addr) {
    asm volatile("ldmatrix.sync.aligned.m8n8.x4.shared.b16 {%0,%1,%2,%3}, [%4];"
                 : "=r"(r[0]), "=r"(r[1]), "=r"(r[2]), "=r"(r[3]) : "r"(addr));
}
__device__ __forceinline__ void mma16816(float* c, const uint* a, const uint* b) {
    asm volatile("mma.sync.aligned.m16n8k16.row.col.f32.bf16.bf16.f32 "
        "{%0,%1,%2,%3},{%4,%5,%6,%7},{%8,%9},{%0,%1,%2,%3};"
        : "+f"(c[0]), "+f"(c[1]), "+f"(c[2]), "+f"(c[3])
        : "r"(a[0]), "r"(a[1]), "r"(a[2]), "r"(a[3]), "r"(b[0]), "r"(b[1]));
}

// ---------------------------------------------------------------------------
// Kernel 1: M = R*E, split to bf16 hi/lo in [d][j] layout.
// ---------------------------------------------------------------------------
__global__ __launch_bounds__(256) void rot_kernel(const float* __restrict__ E,
                                                  const float* __restrict__ theta) {
    __shared__ float sm[8 * 1028];
    const int tid = threadIdx.x;
    const int j0 = blockIdx.x * 8;

    float ct[NQ], st[NQ];
#pragma unroll
    for (int i = 0; i < NQ; i++) sincosf(0.5f * theta[i], &st[i], &ct[i]);

    for (int idx = tid; idx < 8192; idx += 256) {
        int c = idx & 7, d = idx >> 3;
        sm[c * 1028 + d] = E[d * DIM + j0 + c];
    }
    __syncthreads();

    for (int i = 0; i < NQ; i++) {
        const int m = 9 - i;
        for (int t = tid; t < 4096; t += 256) {
            int c = t >> 9, p = t & 511;
            int low = p & ((1 << m) - 1);
            int d0 = ((p >> m) << (m + 1)) | low;
            int d1 = d0 | (1 << m);
            float a0 = sm[c * 1028 + d0];
            float a1 = sm[c * 1028 + d1];
            sm[c * 1028 + d0] = ct[i] * a0 - st[i] * a1;
            sm[c * 1028 + d1] = st[i] * a0 + ct[i] * a1;
        }
        __syncthreads();
    }

    for (int idx = tid; idx < 8192; idx += 256) {
        int c = idx & 7, d = idx >> 3;
        float m = sm[c * 1028 + d];
        __nv_bfloat16 h = __float2bfloat16(m);
        float lo = m - __bfloat162float(h);
        g_Bh[d * DIM + j0 + c] = h;
        g_Bl[d * DIM + j0 + c] = __float2bfloat16(lo);
    }
}

// ---------------------------------------------------------------------------
// Kernel 2: build A = s-state (bf16 hi/lo). One warp per window.
// s_n[j] = Phi[j>>5] * Plo[j&31]; lane l owns Phi[l], Plo[l], shfl-broadcast.
// ---------------------------------------------------------------------------
__global__ __launch_bounds__(128) void state_kernel(const float* __restrict__ x) {
    const int tid = threadIdx.x, lane = tid & 31;
    const int n = blockIdx.x * 4 + (tid >> 5);
    float phi_u = 0.0f, plo_u = 0.0f;
    if (n < NWIN) {
        const int b = n / NWPB;
        const int pos = n - b * NWPB;
        float cs[2][5], sn[2][5];
#pragma unroll
        for (int c = 0; c < 2; c++)
#pragma unroll
            for (int k = 0; k < 5; k++) {
                float v = x[((b * 2 + c) << 12) + pos + k];
                sincosf(0.5f * v, &sn[c][k], &cs[c][k]);
            }
        phi_u = 1.0f; plo_u = 1.0f;
#pragma unroll
        for (int i = 0; i < 5; i++) {
            int bit = (lane >> (4 - i)) & 1;
            phi_u *= bit ? sn[0][i] : cs[0][i];
            plo_u *= bit ? sn[1][i] : cs[1][i];
        }
    }
    __nv_bfloat16* Ah = g_Ah + (size_t)n * DIM;
    __nv_bfloat16* Al = g_Al + (size_t)n * DIM;
#pragma unroll 4
    for (int rep = 0; rep < 32; rep++) {
        float ph = __shfl_sync(0xffffffffu, phi_u, rep);
        float s = ph * plo_u;
        __nv_bfloat16 h = __float2bfloat16(s);
        float lo = s - __bfloat162float(h);
        Ah[rep * 32 + lane] = h;
        Al[rep * 32 + lane] = __float2bfloat16(lo);
    }
}

// ---------------------------------------------------------------------------
// Kernel 3: bf16-split GEMM via mma.sync + signed-square epilogue.
// Block = 128 windows x full 1024 d (8 N=128 chunks). Kc=64 stages, 3-ring.
// Stage layout (64KB): Ah[128][128B] Al Bh Bl, 16B-chunk XOR-(row&7) swizzle.
// ---------------------------------------------------------------------------
#define STG 65536
#define ZSM_OFF (3 * STG)
#define SMEM_BYTES (3 * STG + 512)

__device__ __forceinline__ void load_stage(uint sb, int s, int n0, int tid) {
    const int buf = s % 3;
    const int kc = s & 15, dc = s >> 4;
    const int row = tid >> 1;
    const int cb = (tid & 1) * 4;
    const int r7 = row & 7;
    const uint dbase = sb + (uint)buf * STG + (uint)row * 128;
    const char* aH = (const char*)(g_Ah + (size_t)(n0 + row) * DIM + kc * 64);
    const char* aL = (const char*)(g_Al + (size_t)(n0 + row) * DIM + kc * 64);
    const char* bH = (const char*)(g_Bh + (size_t)(dc * 128 + row) * DIM + kc * 64);
    const char* bL = (const char*)(g_Bl + (size_t)(dc * 128 + row) * DIM + kc * 64);
#pragma unroll
    for (int cc = 0; cc < 4; cc++) {
        int c = cb + cc;
        uint sw = (uint)((c ^ r7) << 4);
        cpasync16(dbase + sw,         aH + c * 16);
        cpasync16(dbase + 16384 + sw, aL + c * 16);
        cpasync16(dbase + 32768 + sw, bH + c * 16);
        cpasync16(dbase + 49152 + sw, bL + c * 16);
    }
    CP_COMMIT;
}

__global__ __launch_bounds__(256, 1) void qmma_kernel(float* __restrict__ out) {
    extern __shared__ __align__(128) char smem[];
    const uint sb = smem_u32(smem);
    const int tid = threadIdx.x, lane = tid & 31, wid = tid >> 5;
    const int warp_m = wid & 3, warp_n = wid >> 2;
    const int n0 = blockIdx.x * 128;
    float* zsm = (float*)(smem + ZSM_OFF);
    if (tid < 128) zsm[tid] = 0.0f;

    // per-thread ldmatrix addressing constants
    const int arow0 = warp_m * 32 + (lane & 15);     // + 16*i per m-tile
    const int ahi = lane >> 4;                        // k-half select
    int nrow[4];
#pragma unroll
    for (int jj = 0; jj < 4; jj++)
        nrow[jj] = warp_n * 64 + jj * 16 + ((lane >> 4) & 1) * 8 + (lane & 7);
    const int bhi = (lane >> 3) & 1;

    float acc[64];
#pragma unroll
    for (int i = 0; i < 64; i++) acc[i] = 0.0f;

    load_stage(sb, 0, n0, tid);
    load_stage(sb, 1, n0, tid);

    for (int s = 0; s < 128; s++) {
        if (s < 126) CP_WAIT1; else CP_WAIT0;
        __syncthreads();
        if (s + 2 < 128) load_stage(sb, s + 2, n0, tid);

        const uint abase = sb + (uint)(s % 3) * STG;
        const uint bbase = abase + 32768;
#pragma unroll
        for (int ks = 0; ks < 4; ks++) {
            uint ah[8], al[8], bh[16], bl[16];
#pragma unroll
            for (int i = 0; i < 2; i++) {
                int row = arow0 + 16 * i;
                uint off = (uint)row * 128 + (uint)(((ks * 2 + ahi) ^ (row & 7)) << 4);
                ldsm4(&ah[i * 4], abase + off);
                ldsm4(&al[i * 4], abase + 16384 + off);
            }
#pragma unroll
            for (int jj = 0; jj < 4; jj++) {
                uint off = (uint)nrow[jj] * 128 + (uint)(((ks * 2 + bhi) ^ (nrow[jj] & 7)) << 4);
                ldsm4(&bh[jj * 4], bbase + off);
                ldsm4(&bl[jj * 4], bbase + 16384 + off);
            }
#pragma unroll
            for (int i = 0; i < 2; i++)
#pragma unroll
                for (int j = 0; j < 8; j++) {
                    float* c = &acc[(i * 8 + j) * 4];
                    mma16816(c, &ah[i * 4], &bh[j * 2]);
                    mma16816(c, &ah[i * 4], &bl[j * 2]);
                    mma16816(c, &al[i * 4], &bh[j * 2]);
                }
        }

        if ((s & 15) == 15) {                        // end of d-chunk
            const float sgn = ((s >> 4) < 4) ? 1.0f : -1.0f;
#pragma unroll
            for (int i = 0; i < 2; i++) {
                float r0 = 0.0f, r1 = 0.0f;
#pragma unroll
                for (int j = 0; j < 8; j++) {
                    float* c = &acc[(i * 8 + j) * 4];
                    r0 = fmaf(c[0], c[0], fmaf(c[1], c[1], r0));
                    r1 = fmaf(c[2], c[2], fmaf(c[3], c[3], r1));
                }
                r0 += __shfl_xor_sync(0xffffffffu, r0, 1);
                r0 += __shfl_xor_sync(0xffffffffu, r0, 2);
                r1 += __shfl_xor_sync(0xffffffffu, r1, 1);
                r1 += __shfl_xor_sync(0xffffffffu, r1, 2);
                if ((lane & 3) == 0) {
                    int mrow = warp_m * 32 + i * 16 + (lane >> 2);
                    atomicAdd(&zsm[mrow],     sgn * r0);
                    atomicAdd(&zsm[mrow + 8], sgn * r1);
                }
            }
#pragma unroll
            for (int i = 0; i < 64; i++) acc[i] = 0.0f;
        }
    }

    __syncthreads();
    if (tid < 128) {
        int n = n0 + tid;
        if (n < NWIN) out[n] = zsm[tid];
    }
}

// ---------------------------------------------------------------------------
extern "C" void kernel_launch(void* const* d_in, const int* in_sizes, int n_in,
                              void* d_out, int out_size) {
    const float* x     = (const float*)d_in[0];
    const float* E     = (const float*)d_in[1];
    const float* theta = (const float*)d_in[2];
    float* out = (float*)d_out;

    rot_kernel<<<DIM / 8, 256>>>(E, theta);
    state_kernel<<<NPAD / 4, 128>>>(x);

    cudaFuncSetAttribute(qmma_kernel,
                         cudaFuncAttributeMaxDynamicSharedMemorySize, SMEM_BYTES);
    qmma_kernel<<<NPAD / 128, 256, SMEM_BYTES>>>(out);
}